// round 8
// baseline (speedup 1.0000x reference)
#include <cuda_runtime.h>
#include <cuda_bf16.h>
#include <math_constants.h>
#include <cstdint>

#define BATCH 4
#define SEQ   2048
#define DIM   1024
#define K3P   (3 * DIM)   // 3072
#define K3S   (3 * SEQ)   // 6144

#define BM 128
#define BN 128
#define BK 64
#define THREADS 128        // 4 warps, warp tile 64x64
#define STAGES 3
#define A_STAGE_BYTES 18432u           // 128 rows x 72 elems x 2B (144B stride)
#define STAGE_BYTES   36864u           // A + B region per stage
#define SMEM_TOTAL (STAGES * STAGE_BYTES)   // 110592 -> 2 CTA/SM

// ---------------- scratch ----------------
__device__ __nv_bfloat16 g_x2 [(long)BATCH * SEQ * K3P];
__device__ __nv_bfloat16 g_Wq2[(long)DIM * K3P];
__device__ __nv_bfloat16 g_Wk2[(long)DIM * K3P];
__device__ __nv_bfloat16 g_Wv2[(long)DIM * K3P];
__device__ __nv_bfloat16 g_Q2 [(long)BATCH * SEQ * K3P];
__device__ __nv_bfloat16 g_K2 [(long)BATCH * SEQ * K3P];
__device__ __nv_bfloat16 g_V2 [(long)BATCH * K3S * DIM];
__device__ float         g_S  [(long)BATCH * SEQ * SEQ];
__device__ __nv_bfloat16 g_P2 [(long)BATCH * SEQ * K3S];

// ---------------- asm helpers ----------------
__device__ __forceinline__ uint32_t smem_u32(const void* p) {
    uint32_t a;
    asm("{ .reg .u64 t; cvta.to.shared.u64 t, %1; cvt.u32.u64 %0, t; }" : "=r"(a) : "l"(p));
    return a;
}
#define LDMX4(r0,r1,r2,r3,addr) \
    asm volatile("ldmatrix.sync.aligned.m8n8.x4.shared.b16 {%0,%1,%2,%3}, [%4];" \
                 : "=r"(r0),"=r"(r1),"=r"(r2),"=r"(r3) : "r"(addr))
#define LDMX4T(r0,r1,r2,r3,addr) \
    asm volatile("ldmatrix.sync.aligned.m8n8.x4.trans.shared.b16 {%0,%1,%2,%3}, [%4];" \
                 : "=r"(r0),"=r"(r1),"=r"(r2),"=r"(r3) : "r"(addr))
#define MMA(c,a,b0,b1) \
    asm volatile("mma.sync.aligned.m16n8k16.row.col.f32.bf16.bf16.f32 " \
                 "{%0,%1,%2,%3}, {%4,%5,%6,%7}, {%8,%9}, {%0,%1,%2,%3};" \
                 : "+f"((c)[0]),"+f"((c)[1]),"+f"((c)[2]),"+f"((c)[3]) \
                 : "r"((a)[0]),"r"((a)[1]),"r"((a)[2]),"r"((a)[3]),"r"(b0),"r"(b1))
#define CPASYNC(s,g) \
    asm volatile("cp.async.cg.shared.global [%0], [%1], 16;" :: "r"(s),"l"(g))
#define CP_COMMIT() asm volatile("cp.async.commit_group;" ::: "memory")
#define CP_WAIT(N)  asm volatile("cp.async.wait_group %0;" :: "n"(N) : "memory")

__device__ __forceinline__ void split_us(float v, unsigned short& h, unsigned short& l) {
    __nv_bfloat16 hb = __float2bfloat16(v);
    __nv_bfloat16 lb = __float2bfloat16(v - __bfloat162float(hb));
    h = __bfloat16_as_ushort(hb);
    l = __bfloat16_as_ushort(lb);
}

__device__ __forceinline__ void store_split_pair(uint32_t* p, float v0, float v1, int lay) {
    unsigned short h0, l0, h1, l1;
    split_us(v0, h0, l0);
    split_us(v1, h1, l1);
    if (lay == 1) {        // A-layout hi,lo,hi
        p[0] = (uint32_t)h0 | ((uint32_t)l0 << 16);
        p[1] = (uint32_t)h0 | ((uint32_t)h1 << 16);
        p[2] = (uint32_t)l1 | ((uint32_t)h1 << 16);
    } else {               // B-layout hi,hi,lo
        p[0] = (uint32_t)h0 | ((uint32_t)h0 << 16);
        p[1] = (uint32_t)l0 | ((uint32_t)h1 << 16);
        p[2] = (uint32_t)h1 | ((uint32_t)l1 << 16);
    }
}

// ---------------- input conversions ----------------
__global__ void convert_x(const float4* __restrict__ in, uint2* __restrict__ out, long n4) {
    long i = (long)blockIdx.x * blockDim.x + threadIdx.x;
    if (i >= n4) return;
    float4 v = in[i];
    unsigned short h[4], l[4];
    split_us(v.x, h[0], l[0]); split_us(v.y, h[1], l[1]);
    split_us(v.z, h[2], l[2]); split_us(v.w, h[3], l[3]);
    unsigned short t[12];
    #pragma unroll
    for (int e = 0; e < 4; e++) { t[3*e] = h[e]; t[3*e+1] = l[e]; t[3*e+2] = h[e]; }
    uint2* o = out + 3 * i;
    #pragma unroll
    for (int j = 0; j < 3; j++) {
        uint2 u;
        u.x = (uint32_t)t[4*j]   | ((uint32_t)t[4*j+1] << 16);
        u.y = (uint32_t)t[4*j+2] | ((uint32_t)t[4*j+3] << 16);
        o[j] = u;
    }
}

__global__ void convert_w(const float4* __restrict__ wq, const float4* __restrict__ wk,
                          const float4* __restrict__ wv,
                          uint2* __restrict__ oq, uint2* __restrict__ ok,
                          uint2* __restrict__ ov, long n4) {
    long i = (long)blockIdx.x * blockDim.x + threadIdx.x;
    if (i >= n4) return;
    const float4* in = (blockIdx.y == 0) ? wq : (blockIdx.y == 1) ? wk : wv;
    uint2* out = (blockIdx.y == 0) ? oq : (blockIdx.y == 1) ? ok : ov;
    float4 v = in[i];
    unsigned short h[4], l[4];
    split_us(v.x, h[0], l[0]); split_us(v.y, h[1], l[1]);
    split_us(v.z, h[2], l[2]); split_us(v.w, h[3], l[3]);
    unsigned short t[12];
    #pragma unroll
    for (int e = 0; e < 4; e++) { t[3*e] = h[e]; t[3*e+1] = h[e]; t[3*e+2] = l[e]; }
    uint2* o = out + 3 * i;
    #pragma unroll
    for (int j = 0; j < 3; j++) {
        uint2 u;
        u.x = (uint32_t)t[4*j]   | ((uint32_t)t[4*j+1] << 16);
        u.y = (uint32_t)t[4*j+2] | ((uint32_t)t[4*j+3] << 16);
        o[j] = u;
    }
}

// ================= GEMM engine (4 warps, 64x64 warptile, frag pipeline) =================
// fragment loads for one ks slice into buffer bf/af[buf]
#define LOADFRAG_NT(aoff, boff, ks, buf)                                                \
    {                                                                                   \
        _Pragma("unroll")                                                               \
        for (int mi = 0; mi < 4; mi++)                                                  \
            LDMX4(af[buf][mi][0], af[buf][mi][1], af[buf][mi][2], af[buf][mi][3],       \
                  (aoff) + (uint32_t)(((wm2 * 64 + mi * 16 + l15) * 72 + lh * 8 + (ks) * 16) * 2)); \
        _Pragma("unroll")                                                               \
        for (int j2 = 0; j2 < 4; j2++)                                                  \
            LDMX4(bf[buf][j2][0], bf[buf][j2][1], bf[buf][j2][2], bf[buf][j2][3],       \
                  (boff) + (uint32_t)(((wn2 * 64 + j2 * 16 + l15) * 72 + lh * 8 + (ks) * 16) * 2)); \
    }

#define LOADFRAG_NN(aoff, boff, ks, buf)                                                \
    {                                                                                   \
        _Pragma("unroll")                                                               \
        for (int mi = 0; mi < 4; mi++)                                                  \
            LDMX4(af[buf][mi][0], af[buf][mi][1], af[buf][mi][2], af[buf][mi][3],       \
                  (aoff) + (uint32_t)(((wm2 * 64 + mi * 16 + l15) * 72 + lh * 8 + (ks) * 16) * 2)); \
        _Pragma("unroll")                                                               \
        for (int j2 = 0; j2 < 4; j2++)                                                  \
            LDMX4T(bf[buf][j2][0], bf[buf][j2][1], bf[buf][j2][2], bf[buf][j2][3],      \
                  (boff) + (uint32_t)((((ks) * 16 + l15) * 136 + wn2 * 64 + j2 * 16 + lh * 8) * 2)); \
    }

// NT: b pairs = (r0,r2) and (r1,r3); NN (trans): (r0,r1) and (r2,r3)
#define COMPUTE_BODY(LOADFRAG, B0A, B0B, B1A, B1B)                                      \
    {                                                                                   \
        uint32_t af[2][4][4], bf[2][4][4];                                              \
        LOADFRAG(aoff_, boff_, 0, 0);                                                   \
        _Pragma("unroll")                                                               \
        for (int ks = 0; ks < 4; ks++) {                                                \
            const int cur = ks & 1;                                                     \
            if (ks < 3) LOADFRAG(aoff_, boff_, ks + 1, cur ^ 1);                        \
            _Pragma("unroll")                                                           \
            for (int mi = 0; mi < 4; mi++) {                                            \
                _Pragma("unroll")                                                       \
                for (int j2 = 0; j2 < 4; j2++) {                                        \
                    MMA(acc[mi][2*j2],   af[cur][mi], bf[cur][j2][B0A], bf[cur][j2][B0B]); \
                    MMA(acc[mi][2*j2+1], af[cur][mi], bf[cur][j2][B1A], bf[cur][j2][B1B]); \
                }                                                                       \
            }                                                                           \
        }                                                                               \
    }

#define COMPUTE_NT() COMPUTE_BODY(LOADFRAG_NT, 0, 2, 1, 3)
#define COMPUTE_NN() COMPUTE_BODY(LOADFRAG_NN, 0, 1, 2, 3)

#define MAINLOOP(NTtiles, LOADFN, COMPUTE_MACRO)                                        \
    LOADFN(0, 0);                                                                       \
    LOADFN(1, 1);                                                                       \
    {                                                                                   \
        int cs = 0;                                                                     \
        for (int t = 0; t < (NTtiles); t++) {                                           \
            if (t + 2 < (NTtiles)) { CP_WAIT(1); } else { CP_WAIT(0); }                 \
            __syncthreads();                                                            \
            int ldst = cs + 2; if (ldst >= 3) ldst -= 3;                                \
            if (t + 2 < (NTtiles)) LOADFN(t + 2, ldst);                                 \
            const uint32_t aoff_ = sbase + (uint32_t)cs * STAGE_BYTES;                  \
            const uint32_t boff_ = aoff_ + A_STAGE_BYTES;                               \
            COMPUTE_MACRO();                                                            \
            cs = (cs == 2) ? 0 : cs + 1;                                                \
        }                                                                               \
    }

#define ACC_DECL                                                                        \
    float acc[4][8][4];                                                                 \
    _Pragma("unroll")                                                                   \
    for (int i = 0; i < 4; i++)                                                         \
        _Pragma("unroll")                                                               \
        for (int j = 0; j < 8; j++)                                                     \
            _Pragma("unroll")                                                           \
            for (int r = 0; r < 4; r++) acc[i][j][r] = 0.f;

// ---------------- merged QKV projection ----------------
__global__ void __launch_bounds__(THREADS, 2)
qkv_gemm(const __nv_bfloat16* __restrict__ A,
         const __nv_bfloat16* __restrict__ Wq, const __nv_bfloat16* __restrict__ Wk,
         const __nv_bfloat16* __restrict__ Wv,
         __nv_bfloat16* __restrict__ Qo, __nv_bfloat16* __restrict__ Ko,
         __nv_bfloat16* __restrict__ Vo)
{
    extern __shared__ char smem[];
    const uint32_t sbase = smem_u32(smem);

    const int wsel = blockIdx.x >> 3;
    const __nv_bfloat16* B = (wsel == 0) ? Wq : (wsel == 1) ? Wk : Wv;

    const int tid = threadIdx.x, lid = tid & 31, wid = tid >> 5;
    const int wm2 = wid & 1, wn2 = wid >> 1;
    const int row0 = blockIdx.y * BM, col0 = (blockIdx.x & 7) * BN;
    const int nT = K3P / BK;   // 48

    ACC_DECL;

    auto LOAD = [&](int t, int st) {
        const long kt = (long)t * BK;
        const uint32_t aoff = sbase + (uint32_t)st * STAGE_BYTES;
        const uint32_t boff = aoff + A_STAGE_BYTES;
        #pragma unroll
        for (int i = 0; i < 8; i++) {
            int idx = tid + i * THREADS;
            int row = idx >> 3, q = idx & 7;
            CPASYNC(aoff + (uint32_t)(row * 144 + q * 16),
                    A + (long)(row0 + row) * K3P + kt + q * 8);
            CPASYNC(boff + (uint32_t)(row * 144 + q * 16),
                    B + (long)(col0 + row) * K3P + kt + q * 8);
        }
        CP_COMMIT();
    };

    const int l15 = lid & 15, lh = lid >> 4;

    MAINLOOP(nT, LOAD, COMPUTE_NT);

    const int g = lid >> 2, tig = lid & 3;
    #pragma unroll
    for (int mi = 0; mi < 4; mi++) {
        #pragma unroll
        for (int j = 0; j < 8; j++) {
            const int c = col0 + wn2 * 64 + j * 8 + 2 * tig;
            #pragma unroll
            for (int s = 0; s < 2; s++) {
                const int r = row0 + wm2 * 64 + mi * 16 + g + s * 8;
                const float v0 = acc[mi][j][2*s], v1 = acc[mi][j][2*s+1];
                if (wsel == 0) {
                    store_split_pair(reinterpret_cast<uint32_t*>(Qo + (long)r * K3P + 3L * c), v0, v1, 1);
                } else if (wsel == 1) {
                    store_split_pair(reinterpret_cast<uint32_t*>(Ko + (long)r * K3P + 3L * c), v0, v1, 2);
                } else {
                    unsigned short h0, l0, h1, l1;
                    split_us(v0, h0, l0);
                    split_us(v1, h1, l1);
                    const int bz = r >> 11, tok = r & (SEQ - 1);
                    __nv_bfloat16* Vb = Vo + (long)bz * K3S * DIM;
                    uint32_t uh = (uint32_t)h0 | ((uint32_t)h1 << 16);
                    uint32_t ul = (uint32_t)l0 | ((uint32_t)l1 << 16);
                    long rb = (long)(3 * tok) * DIM + c;
                    *reinterpret_cast<uint32_t*>(&Vb[rb])           = uh;
                    *reinterpret_cast<uint32_t*>(&Vb[rb + DIM])     = uh;
                    *reinterpret_cast<uint32_t*>(&Vb[rb + 2 * DIM]) = ul;
                }
            }
        }
    }
}

// ---------------- scores GEMM: triangular-packed grid ----------------
__global__ void __launch_bounds__(THREADS, 2)
scores_gemm(const __nv_bfloat16* __restrict__ Q, const __nv_bfloat16* __restrict__ Kk,
            float* __restrict__ Sc, float alpha)
{
    extern __shared__ char smem[];
    const uint32_t sbase = smem_u32(smem);

    int t_lin = blockIdx.x;
    int by = (int)((sqrtf(8.f * t_lin + 1.f) - 1.f) * 0.5f);
    while ((by + 1) * (by + 2) / 2 <= t_lin) by++;
    while (by * (by + 1) / 2 > t_lin) by--;
    const int bx = t_lin - by * (by + 1) / 2;

    const __nv_bfloat16* A = Q  + (long)blockIdx.z * SEQ * K3P;
    const __nv_bfloat16* B = Kk + (long)blockIdx.z * SEQ * K3P;
    float* C = Sc + (long)blockIdx.z * SEQ * SEQ;

    const int tid = threadIdx.x, lid = tid & 31, wid = tid >> 5;
    const int wm2 = wid & 1, wn2 = wid >> 1;
    const int row0 = by * BM, col0 = bx * BN;
    const int nT = K3P / BK;

    ACC_DECL;

    auto LOAD = [&](int t, int st) {
        const long kt = (long)t * BK;
        const uint32_t aoff = sbase + (uint32_t)st * STAGE_BYTES;
        const uint32_t boff = aoff + A_STAGE_BYTES;
        #pragma unroll
        for (int i = 0; i < 8; i++) {
            int idx = tid + i * THREADS;
            int row = idx >> 3, q = idx & 7;
            CPASYNC(aoff + (uint32_t)(row * 144 + q * 16),
                    A + (long)(row0 + row) * K3P + kt + q * 8);
            CPASYNC(boff + (uint32_t)(row * 144 + q * 16),
                    B + (long)(col0 + row) * K3P + kt + q * 8);
        }
        CP_COMMIT();
    };

    const int l15 = lid & 15, lh = lid >> 4;

    MAINLOOP(nT, LOAD, COMPUTE_NT);

    const int g = lid >> 2, tig = lid & 3;
    #pragma unroll
    for (int mi = 0; mi < 4; mi++) {
        #pragma unroll
        for (int j = 0; j < 8; j++) {
            const int c = col0 + wn2 * 64 + j * 8 + 2 * tig;
            #pragma unroll
            for (int s = 0; s < 2; s++) {
                const int r = row0 + wm2 * 64 + mi * 16 + g + s * 8;
                float2 o = make_float2(acc[mi][j][2*s] * alpha, acc[mi][j][2*s+1] * alpha);
                *reinterpret_cast<float2*>(&C[(long)r * SEQ + c]) = o;
            }
        }
    }
}

// ---------------- PV GEMM: NN, causal k-limit, longest-first ----------------
__global__ void __launch_bounds__(THREADS, 2)
pv_gemm(const __nv_bfloat16* __restrict__ P, const __nv_bfloat16* __restrict__ V,
        float* __restrict__ Out)
{
    extern __shared__ char smem[];
    const uint32_t sbase = smem_u32(smem);

    const int by = gridDim.y - 1 - blockIdx.y;
    const __nv_bfloat16* A = P + (long)blockIdx.z * SEQ * K3S;
    const __nv_bfloat16* B = V + (long)blockIdx.z * K3S * DIM;
    float* C = Out + (long)blockIdx.z * SEQ * DIM;

    const int tid = threadIdx.x, lid = tid & 31, wid = tid >> 5;
    const int wm2 = wid & 1, wn2 = wid >> 1;
    const int row0 = by * BM, col0 = blockIdx.x * BN;
    const int nT = 3 * (by + 1) * BM / BK;        // 6*(by+1) >= 6

    ACC_DECL;

    auto LOAD = [&](int t, int st) {
        const long kt = (long)t * BK;
        const uint32_t aoff = sbase + (uint32_t)st * STAGE_BYTES;
        const uint32_t boff = aoff + A_STAGE_BYTES;
        #pragma unroll
        for (int i = 0; i < 8; i++) {
            int idx = tid + i * THREADS;
            int row = idx >> 3, q = idx & 7;
            CPASYNC(aoff + (uint32_t)(row * 144 + q * 16),
                    A + (long)(row0 + row) * K3S + kt + q * 8);
            int kr = idx >> 4, c = (idx & 15) * 8;
            CPASYNC(boff + (uint32_t)(kr * 272 + c * 2),
                    B + (long)(kt + kr) * DIM + col0 + c);
        }
        CP_COMMIT();
    };

    const int l15 = lid & 15, lh = lid >> 4;

    MAINLOOP(nT, LOAD, COMPUTE_NN);

    const int g = lid >> 2, tig = lid & 3;
    #pragma unroll
    for (int mi = 0; mi < 4; mi++) {
        #pragma unroll
        for (int j = 0; j < 8; j++) {
            const int c = col0 + wn2 * 64 + j * 8 + 2 * tig;
            #pragma unroll
            for (int s = 0; s < 2; s++) {
                const int r = row0 + wm2 * 64 + mi * 16 + g + s * 8;
                float2 o = make_float2(acc[mi][j][2*s], acc[mi][j][2*s+1]);
                *reinterpret_cast<float2*>(&C[(long)r * DIM + c]) = o;
            }
        }
    }
}

// ---------------- softmax: fp32 scores -> split-bf16 P (A-layout) ----------------
// Writes P only up to the causal 128-block boundary (PV never reads beyond it).
__global__ __launch_bounds__(256)
void softmax_p2(const float* __restrict__ Sc, const int* __restrict__ mask,
                __nv_bfloat16* __restrict__ P2)
{
    __shared__ float e[SEQ];
    __shared__ float red[256];
    const int q = SEQ - 1 - blockIdx.x;
    const int b = blockIdx.y, tid = threadIdx.x;
    const float* row = Sc + ((long)b * SEQ + q) * SEQ;
    const int* mk = mask + (long)b * SEQ;
    __nv_bfloat16* pr = P2 + ((long)b * SEQ + q) * (long)K3S;
    const int qe = ((q >> 7) + 1) << 7;    // block-aligned end

    float mx = -CUDART_INF_F;
    for (int c = tid; c <= q; c += 256)
        if (mk[c]) mx = fmaxf(mx, row[c]);
    red[tid] = mx; __syncthreads();
    #pragma unroll
    for (int s = 128; s > 0; s >>= 1) {
        if (tid < s) red[tid] = fmaxf(red[tid], red[tid + s]);
        __syncthreads();
    }
    mx = red[0]; __syncthreads();

    float sum = 0.f;
    for (int c = tid; c <= q; c += 256) {
        float v = mk[c] ? __expf(row[c] - mx) : 0.f;
        e[c] = v; sum += v;
    }
    red[tid] = sum; __syncthreads();
    #pragma unroll
    for (int s = 128; s > 0; s >>= 1) {
        if (tid < s) red[tid] += red[tid + s];
        __syncthreads();
    }
    const float inv = 1.f / red[0];
    __syncthreads();

    for (int c = tid; c < qe; c += 256) {
        float v = (c <= q) ? e[c] * inv : 0.f;
        unsigned short h, l;
        split_us(v, h, l);
        pr[3*c]   = __ushort_as_bfloat16(h);
        pr[3*c+1] = __ushort_as_bfloat16(l);
        pr[3*c+2] = __ushort_as_bfloat16(h);
    }
}

// ---------------- host ----------------
extern "C" void kernel_launch(void* const* d_in, const int* in_sizes, int n_in,
                              void* d_out, int out_size)
{
    const float* x    = (const float*)d_in[0];
    const int*   mask = (const int*)  d_in[1];
    const float* Wq   = (const float*)d_in[2];
    const float* Wk   = (const float*)d_in[3];
    const float* Wv   = (const float*)d_in[4];
    float* out = (float*)d_out;

    __nv_bfloat16 *x2p, *wq2, *wk2, *wv2, *q2p, *k2p, *v2p, *p2p;
    float* sp;
    cudaGetSymbolAddress((void**)&x2p, g_x2);
    cudaGetSymbolAddress((void**)&wq2, g_Wq2);
    cudaGetSymbolAddress((void**)&wk2, g_Wk2);
    cudaGetSymbolAddress((void**)&wv2, g_Wv2);
    cudaGetSymbolAddress((void**)&q2p, g_Q2);
    cudaGetSymbolAddress((void**)&k2p, g_K2);
    cudaGetSymbolAddress((void**)&v2p, g_V2);
    cudaGetSymbolAddress((void**)&sp,  g_S);
    cudaGetSymbolAddress((void**)&p2p, g_P2);

    static bool attr_done = false;
    if (!attr_done) {
        cudaFuncSetAttribute(qkv_gemm,    cudaFuncAttributeMaxDynamicSharedMemorySize, SMEM_TOTAL);
        cudaFuncSetAttribute(scores_gemm, cudaFuncAttributeMaxDynamicSharedMemorySize, SMEM_TOTAL);
        cudaFuncSetAttribute(pv_gemm,     cudaFuncAttributeMaxDynamicSharedMemorySize, SMEM_TOTAL);
        attr_done = true;
    }

    const long nx4 = (long)BATCH * SEQ * DIM / 4;
    const long nw4 = (long)DIM * DIM / 4;
    convert_x<<<(unsigned)((nx4 + 255) / 256), 256>>>((const float4*)x, (uint2*)x2p, nx4);
    convert_w<<<dim3((unsigned)((nw4 + 255) / 256), 3), 256>>>(
        (const float4*)Wq, (const float4*)Wk, (const float4*)Wv,
        (uint2*)wq2, (uint2*)wk2, (uint2*)wv2, nw4);

    // merged QKV projections
    dim3 gP(24, (BATCH * SEQ) / BM, 1);                  // (24, 64)
    qkv_gemm<<<gP, THREADS, SMEM_TOTAL>>>(x2p, wq2, wk2, wv2, q2p, k2p, v2p);

    // scores: triangular-packed grid
    dim3 gS(136, 1, BATCH);
    scores_gemm<<<gS, THREADS, SMEM_TOTAL>>>(q2p, k2p, sp, 1.f / 32.f);

    // softmax -> split P
    softmax_p2<<<dim3(SEQ, BATCH), 256>>>(sp, mask, p2p);

    // O = P @ V
    dim3 gO(DIM / BN, SEQ / BM, BATCH);                  // (8, 16, 4)
    pv_gemm<<<gO, THREADS, SMEM_TOTAL>>>(p2p, v2p, out);
}